// round 3
// baseline (speedup 1.0000x reference)
#include <cuda_runtime.h>
#include <cuda_bf16.h>
#include <cstdint>

// ============================================================================
// Problem constants
// ============================================================================
#define BB       512
#define TT       100
#define NPRE     256
#define NPOST    256
#define KTOT     (BB * TT)        // 51200
#define KTILE    64
#define NTILES   (KTOT / KTILE)   // 800
#define KSPLIT   74               // grid (74, 2 mtiles) = 148 CTAs = one wave

// A smem tile: 128 rows x 64 bf16, padded row stride 144B
#define A_ROW_B   144
#define A_TILE_B  (128 * A_ROW_B)        // 18432
// B smem tile (bf16, [k][q]): 64 rows x 256 bf16, padded stride 528B
#define B_ROW_B   528
#define B_TILE_B  (64 * B_ROW_B)         // 33792
// B fp32 staging: 64 rows x 256 f32, padded stride 1040B
#define S_ROW_B   1040
#define S_TILE_B  (64 * S_ROW_B)         // 66560

#define SM_A0     0
#define SM_A1     A_TILE_B
#define SM_B0     (2 * A_TILE_B)                  // 36864
#define SM_B1     (2 * A_TILE_B + B_TILE_B)       // 70656
#define SM_STAGE  (2 * A_TILE_B + 2 * B_TILE_B)   // 104448
#define GEMM_SMEM (SM_STAGE + S_TILE_B)           // 171008

// ============================================================================
// PTX helpers (baseline PTX only — no tcgen05 on plain sm_103 target)
// ============================================================================
__device__ __forceinline__ uint32_t smem_to_u32(const void* smem_ptr) {
    uint32_t addr;
    asm("{ .reg .u64 tmp; cvta.to.shared.u64 tmp, %1; cvt.u32.u64 %0, tmp; }"
        : "=r"(addr) : "l"(smem_ptr));
    return addr;
}

__device__ __forceinline__ void cp_async_16(uint32_t dst_smem, const void* src) {
    asm volatile("cp.async.cg.shared.global [%0], [%1], 16;"
                 :: "r"(dst_smem), "l"(src) : "memory");
}
#define CP_ASYNC_COMMIT() asm volatile("cp.async.commit_group;" ::: "memory")
#define CP_ASYNC_WAIT0()  asm volatile("cp.async.wait_group 0;" ::: "memory")

__device__ __forceinline__ void ldmatrix_x4(uint32_t* r, uint32_t addr) {
    asm volatile("ldmatrix.sync.aligned.m8n8.x4.shared.b16 {%0,%1,%2,%3}, [%4];"
                 : "=r"(r[0]), "=r"(r[1]), "=r"(r[2]), "=r"(r[3]) : "r"(addr));
}
__device__ __forceinline__ void ldmatrix_x4_trans(uint32_t* r, uint32_t addr) {
    asm volatile("ldmatrix.sync.aligned.m8n8.x4.trans.shared.b16 {%0,%1,%2,%3}, [%4];"
                 : "=r"(r[0]), "=r"(r[1]), "=r"(r[2]), "=r"(r[3]) : "r"(addr));
}

__device__ __forceinline__ void mma_16816(float* c, const uint32_t* a, const uint32_t* b) {
    asm volatile(
        "mma.sync.aligned.m16n8k16.row.col.f32.bf16.bf16.f32 "
        "{%0,%1,%2,%3}, {%4,%5,%6,%7}, {%8,%9}, {%0,%1,%2,%3};"
        : "+f"(c[0]), "+f"(c[1]), "+f"(c[2]), "+f"(c[3])
        : "r"(a[0]), "r"(a[1]), "r"(a[2]), "r"(a[3]), "r"(b[0]), "r"(b[1]));
}

// ============================================================================
// Scratch (device globals — sanctioned no-alloc workaround)
// ============================================================================
__device__ __nv_bfloat16 g_trace[(size_t)NPRE * KTOT];                 // [p][k] bf16
__device__ float         g_partials[(size_t)KSPLIT * NPRE * NPOST];    // 19.4 MB

// ============================================================================
// Kernel 1: exponential pre-trace + transpose to [p][k] bf16
//   grid = 512 (one CTA per batch b), 256 threads (one per p)
// ============================================================================
__global__ void stdp_trace_kernel(const float* __restrict__ pre) {
    __shared__ __nv_bfloat16 tile[256 * 54];
    const int b = blockIdx.x;
    const int p = threadIdx.x;
    const float d = 0.95122942450071403f;  // exp(-1/20)

    const float* src = pre + (size_t)b * (TT * NPRE) + p;
    float carry = 0.0f;

    const int wid  = threadIdx.x >> 5;
    const int lane = threadIdx.x & 31;

    #pragma unroll
    for (int half = 0; half < 2; ++half) {
        const int t0 = half * 50;
        #pragma unroll
        for (int tt = 0; tt < 50; ++tt) {
            float x = src[(size_t)(t0 + tt) * NPRE];
            tile[p * 54 + tt] = __float2bfloat16(carry);   // trace[t] = carry
            carry = d * (carry + x);
        }
        __syncthreads();
        if (lane < 25) {
            for (int row = wid; row < 256; row += 8) {
                uint32_t v = *(const uint32_t*)&tile[row * 54 + lane * 2];
                *(uint32_t*)((char*)(g_trace + (size_t)row * KTOT + (size_t)b * TT + t0) + lane * 4) = v;
            }
        }
        __syncthreads();
    }
}

// ============================================================================
// Kernel 2: split-K bf16 HMMA GEMM, CTA tile 128x256, fused post convert
//   D[p,q] += sum_k trace[p,k] * post[k,q]
//   grid (KSPLIT=74, mtile=2), 512 threads = 16 warps (2 M x 8 N), warp 64x32
// ============================================================================
__global__ void __launch_bounds__(512, 1) stdp_gemm_kernel(const float* __restrict__ post) {
    extern __shared__ __align__(16) char smem[];
    const uint32_t su = smem_to_u32(smem);

    const int tid    = threadIdx.x;
    const int wid    = tid >> 5;
    const int lane   = tid & 31;
    const int kid    = blockIdx.x;
    const int mtile  = blockIdx.y;
    const int warp_m = wid >> 3;       // 0..1  (64 rows)
    const int warp_n = wid & 7;        // 0..7  (32 cols)

    const __nv_bfloat16* a_base = g_trace + (size_t)(mtile * 128) * KTOT;

    const uint32_t smA[2] = { su + SM_A0, su + SM_A1 };
    const uint32_t smB[2] = { su + SM_B0, su + SM_B1 };
    const uint32_t smS    = su + SM_STAGE;

    float acc[4][4][4];
    #pragma unroll
    for (int i = 0; i < 4; ++i)
        #pragma unroll
        for (int j = 0; j < 4; ++j)
            #pragma unroll
            for (int c = 0; c < 4; ++c) acc[i][j][c] = 0.0f;

    const int n_iter = (NTILES - kid + KSPLIT - 1) / KSPLIT;   // 10 or 11

    // issue loads for tile index j: A (bf16, direct) + B fp32 into staging
    auto issue = [&](int j, int abuf) {
        const int k0 = (kid + j * KSPLIT) * KTILE;
        // A: 128 rows x 128B = 1024 chunks / 512 thr = 2 per thread
        #pragma unroll
        for (int it = 0; it < 2; ++it) {
            int idx = tid + it * 512;
            int r   = idx >> 3;
            int c16 = idx & 7;
            cp_async_16(smA[abuf] + (uint32_t)(r * A_ROW_B + c16 * 16),
                        a_base + (size_t)r * KTOT + k0 + c16 * 8);
        }
        // B fp32: 64 rows x 1024B = 4096 chunks / 512 thr = 8 per thread
        #pragma unroll
        for (int it = 0; it < 8; ++it) {
            int idx = tid + it * 512;
            int kk  = idx >> 6;
            int c16 = idx & 63;
            cp_async_16(smS + (uint32_t)(kk * S_ROW_B + c16 * 16),
                        post + (size_t)(k0 + kk) * NPOST + c16 * 4);
        }
        CP_ASYNC_COMMIT();
    };

    // convert staging fp32 -> bf16 buf
    auto convert = [&](int bbuf) {
        #pragma unroll
        for (int it = 0; it < 8; ++it) {
            int idx = tid + it * 512;
            int kk  = idx >> 6;
            int c16 = idx & 63;
            float4 v = *(const float4*)(smem + SM_STAGE + kk * S_ROW_B + c16 * 16);
            uint32_t lo = ((uint32_t)__bfloat16_as_ushort(__float2bfloat16(v.y)) << 16)
                        |  (uint32_t)__bfloat16_as_ushort(__float2bfloat16(v.x));
            uint32_t hi = ((uint32_t)__bfloat16_as_ushort(__float2bfloat16(v.w)) << 16)
                        |  (uint32_t)__bfloat16_as_ushort(__float2bfloat16(v.z));
            uint2 pk = make_uint2(lo, hi);
            *(uint2*)(smem + (bbuf ? SM_B1 : SM_B0) + kk * B_ROW_B + c16 * 8) = pk;
        }
    };

    // ---- prologue ----
    issue(0, 0);
    CP_ASYNC_WAIT0();
    __syncthreads();
    convert(0);
    __syncthreads();
    if (n_iter > 1) issue(1, 1);

    // ldmatrix lane addressing
    const int a_row  = (lane & 15);           // + warp_m*64 + mi*16
    const int a_colh = (lane >> 4) * 8;       // + ks*16   (halves of k16)
    // B (trans): groups of 8 lanes -> (k half, q half)
    const int bg  = lane >> 3;                // 0..3
    const int bl8 = lane & 7;
    const int b_krow = (bg & 1) * 8 + bl8;    // + ks*16
    const int b_qoff = (bg >> 1) * 8;         // + warp_n*32 + nip*16

    for (int i = 0; i < n_iter; ++i) {
        const int buf = i & 1;
        const uint32_t A = smA[buf];
        const uint32_t Bb = smB[buf];

        #pragma unroll
        for (int ks = 0; ks < 4; ++ks) {
            uint32_t afrag[4][4];
            uint32_t bfrag[4][2];
            #pragma unroll
            for (int mi = 0; mi < 4; ++mi) {
                uint32_t addr = A + (uint32_t)((warp_m * 64 + mi * 16 + a_row) * A_ROW_B
                                               + (a_colh + ks * 16) * 2);
                ldmatrix_x4(afrag[mi], addr);
            }
            #pragma unroll
            for (int nip = 0; nip < 2; ++nip) {
                uint32_t addr = Bb + (uint32_t)((ks * 16 + b_krow) * B_ROW_B
                                                + (warp_n * 32 + nip * 16 + b_qoff) * 2);
                uint32_t r[4];
                ldmatrix_x4_trans(r, addr);
                bfrag[nip * 2 + 0][0] = r[0]; bfrag[nip * 2 + 0][1] = r[1];
                bfrag[nip * 2 + 1][0] = r[2]; bfrag[nip * 2 + 1][1] = r[3];
            }
            #pragma unroll
            for (int mi = 0; mi < 4; ++mi)
                #pragma unroll
                for (int ni = 0; ni < 4; ++ni)
                    mma_16816(acc[mi][ni], afrag[mi], bfrag[ni]);
        }

        if (i + 1 < n_iter) {
            CP_ASYNC_WAIT0();          // staging(i+1) + A[(i+1)&1] landed
            __syncthreads();           // all warps done with mma(i) and staging reads
            convert(buf ^ 1);
            __syncthreads();           // convert visible; staging free for reuse
            if (i + 2 < n_iter) issue(i + 2, buf);   // A[buf] safe: mma(i) done
        }
    }

    // ---- epilogue: fp32 partials ----
    float* part = g_partials + (size_t)kid * (NPRE * NPOST);
    const int p_base = mtile * 128 + warp_m * 64;
    const int q_base = warp_n * 32;
    #pragma unroll
    for (int mi = 0; mi < 4; ++mi) {
        #pragma unroll
        for (int ni = 0; ni < 4; ++ni) {
            int p0 = p_base + mi * 16 + (lane >> 2);
            int q  = q_base + ni * 8 + (lane & 3) * 2;
            *(float2*)(part + (size_t)p0 * NPOST + q)       = make_float2(acc[mi][ni][0], acc[mi][ni][1]);
            *(float2*)(part + (size_t)(p0 + 8) * NPOST + q) = make_float2(acc[mi][ni][2], acc[mi][ni][3]);
        }
    }
}

// ============================================================================
// Kernel 3: reduce partials + scale (float4 per thread)
// ============================================================================
__global__ void stdp_reduce_kernel(float* __restrict__ out) {
    const int idx = blockIdx.x * blockDim.x + threadIdx.x;   // 0..16383 (float4)
    const float scale = (0.005f - 0.00525f) / (float)KTOT;
    float4 s = make_float4(0.f, 0.f, 0.f, 0.f);
    #pragma unroll 2
    for (int k = 0; k < KSPLIT; ++k) {
        float4 v = *(const float4*)(g_partials + (size_t)k * (NPRE * NPOST) + idx * 4);
        s.x += v.x; s.y += v.y; s.z += v.z; s.w += v.w;
    }
    s.x *= scale; s.y *= scale; s.z *= scale; s.w *= scale;
    *(float4*)(out + idx * 4) = s;
}

// ============================================================================
// Launch
// ============================================================================
extern "C" void kernel_launch(void* const* d_in, const int* in_sizes, int n_in,
                              void* d_out, int out_size) {
    (void)in_sizes; (void)n_in; (void)out_size;
    const float* pre  = (const float*)d_in[0];
    const float* post = (const float*)d_in[1];
    float* out = (float*)d_out;

    cudaFuncSetAttribute(stdp_gemm_kernel,
                         cudaFuncAttributeMaxDynamicSharedMemorySize, GEMM_SMEM);

    stdp_trace_kernel<<<BB, 256>>>(pre);
    stdp_gemm_kernel<<<dim3(KSPLIT, 2), 512, GEMM_SMEM>>>(post);
    stdp_reduce_kernel<<<64, 256>>>(out);
}

// round 4
// speedup vs baseline: 1.0349x; 1.0349x over previous
#include <cuda_runtime.h>
#include <cuda_bf16.h>
#include <cstdint>

// ============================================================================
// Problem constants
// ============================================================================
#define BB       512
#define TT       100          // K per batch
#define TPAD     112          // padded to 7 x k16
#define NPRE     256
#define NPOST    256
#define KTOT     (BB * TT)    // 51200
#define KSPLIT   74           // grid (74, 2 mtiles) = 148 CTAs = one wave

// A tile (trace bf16, [p][t]): 128 rows, row stride 240B (120 bf16 >= 112)
#define A_ROW_B   240
#define A_TILE_B  (128 * A_ROW_B)       // 30720
// B tile (post bf16, [t][q]): 112 rows, row stride 528B (264 bf16 >= 256)
#define B_ROW_B   528
#define B_TILE_B  (TPAD * B_ROW_B)      // 59136

#define SM_A0     0
#define SM_A1     A_TILE_B                       // 30720
#define SM_B0     (2 * A_TILE_B)                 // 61440
#define SM_B1     (2 * A_TILE_B + B_TILE_B)      // 120576
#define SM_SCAN   (2 * A_TILE_B + 2 * B_TILE_B)  // 179712
#define GEMM_SMEM (SM_SCAN + 4 * 128 * 4)        // 181760

// ============================================================================
// PTX helpers (baseline PTX only — tcgen05 unavailable on plain sm_103 target)
// ============================================================================
__device__ __forceinline__ uint32_t smem_to_u32(const void* smem_ptr) {
    uint32_t addr;
    asm("{ .reg .u64 tmp; cvta.to.shared.u64 tmp, %1; cvt.u32.u64 %0, tmp; }"
        : "=r"(addr) : "l"(smem_ptr));
    return addr;
}

__device__ __forceinline__ void ldmatrix_x4(uint32_t* r, uint32_t addr) {
    asm volatile("ldmatrix.sync.aligned.m8n8.x4.shared.b16 {%0,%1,%2,%3}, [%4];"
                 : "=r"(r[0]), "=r"(r[1]), "=r"(r[2]), "=r"(r[3]) : "r"(addr));
}
__device__ __forceinline__ void ldmatrix_x4_trans(uint32_t* r, uint32_t addr) {
    asm volatile("ldmatrix.sync.aligned.m8n8.x4.trans.shared.b16 {%0,%1,%2,%3}, [%4];"
                 : "=r"(r[0]), "=r"(r[1]), "=r"(r[2]), "=r"(r[3]) : "r"(addr));
}

__device__ __forceinline__ void mma_16816(float* c, const uint32_t* a, const uint32_t* b) {
    asm volatile(
        "mma.sync.aligned.m16n8k16.row.col.f32.bf16.bf16.f32 "
        "{%0,%1,%2,%3}, {%4,%5,%6,%7}, {%8,%9}, {%0,%1,%2,%3};"
        : "+f"(c[0]), "+f"(c[1]), "+f"(c[2]), "+f"(c[3])
        : "r"(a[0]), "r"(a[1]), "r"(a[2]), "r"(a[3]), "r"(b[0]), "r"(b[1]));
}

__device__ __forceinline__ uint32_t pack_bf16x2(float a, float b) {
    return ((uint32_t)__bfloat16_as_ushort(__float2bfloat16(b)) << 16)
         |  (uint32_t)__bfloat16_as_ushort(__float2bfloat16(a));
}

// ============================================================================
// Scratch
// ============================================================================
__device__ float g_partials[(size_t)KSPLIT * NPRE * NPOST];   // 19.4 MB

// ============================================================================
// Fused kernel: trace recurrence + post convert + split-K bf16 HMMA GEMM
//   grid (74, 2), 512 threads = 16 warps (2 M x 8 N), warp tile 64x32
// ============================================================================
__global__ void __launch_bounds__(512, 1) stdp_fused_kernel(
    const float* __restrict__ pre, const float* __restrict__ post)
{
    extern __shared__ __align__(16) char smem[];
    const uint32_t su = smem_to_u32(smem);
    float* scan = (float*)(smem + SM_SCAN);      // [4][128]

    const int tid    = threadIdx.x;
    const int wid    = tid >> 5;
    const int lane   = tid & 31;
    const int kid    = blockIdx.x;
    const int mtile  = blockIdx.y;
    const int warp_m = wid >> 3;       // 0..1
    const int warp_n = wid & 7;        // 0..7

    // trace-compute role: p in [0,128), seg in [0,4) covering 25 t each
    const int tp   = tid & 127;
    const int tseg = tid >> 7;

    const float d   = 0.95122942450071403f;   // exp(-1/20)
    const float d25 = 0.28650479686019010f;   // exp(-25/20)

    const uint32_t smA[2] = { su + SM_A0, su + SM_A1 };
    const uint32_t smB[2] = { su + SM_B0, su + SM_B1 };

    // ---- zero pads (t in [100,TPAD)) once; batches only write t < 100 ----
    for (int i = tid; i < 2 * 128 * 10; i += 512) {      // A: bytes [200,240) per row
        int bufrow = i / 10;            // 0..255 (both buffers)
        int off    = (i % 10) * 4;
        *(uint32_t*)(smem + SM_A0 + bufrow * A_ROW_B + 200 + off) = 0u;
    }
    for (int i = tid; i < 2 * 12 * (B_ROW_B / 4); i += 512) {   // B rows [100,112)
        int half = i / (12 * (B_ROW_B / 4));
        int rem  = i % (12 * (B_ROW_B / 4));
        int row  = 100 + rem / (B_ROW_B / 4);
        int off  = (rem % (B_ROW_B / 4)) * 4;
        *(uint32_t*)(smem + (half ? SM_B1 : SM_B0) + row * B_ROW_B + off) = 0u;
    }

    float acc[4][4][4];
    #pragma unroll
    for (int i = 0; i < 4; ++i)
        #pragma unroll
        for (int j = 0; j < 4; ++j)
            #pragma unroll
            for (int c = 0; c < 4; ++c) acc[i][j][c] = 0.0f;

    const int nb = (BB - kid + KSPLIT - 1) / KSPLIT;   // 6 or 7 batches

    // ---- prepare(batch, buf): build A (trace) and B (post) bf16 tiles ----
    auto prepare = [&](int b, int buf) {
        const uint32_t A = smA[buf];
        const uint32_t Bb = smB[buf];

        // pre loads: thread (tp, tseg) reads 25 consecutive-t values of its p
        float xr[25];
        {
            const float* src = pre + ((size_t)b * TT + tseg * 25) * NPRE + mtile * 128 + tp;
            #pragma unroll
            for (int i = 0; i < 25; ++i)
                xr[i] = src[(size_t)i * NPRE];
        }

        // post: 6400 float4 chunks; convert to bf16, STS into B tile [t][q]
        {
            const float4* psrc = (const float4*)(post + (size_t)b * TT * NPOST);
            #pragma unroll
            for (int it = 0; it < 13; ++it) {
                int f = tid + it * 512;
                if (f < 6400) {
                    int t = f >> 6, qg = f & 63;
                    float4 v = psrc[t * 64 + qg];
                    uint2 pk = make_uint2(pack_bf16x2(v.x, v.y), pack_bf16x2(v.z, v.w));
                    *(uint2*)(smem + (buf ? SM_B1 : SM_B0) + t * B_ROW_B + qg * 8) = pk;
                }
            }
        }

        // phase 1: local decayed sum over this segment (zero-init carry)
        float c = 0.0f;
        #pragma unroll
        for (int i = 0; i < 25; ++i)
            c = d * (c + xr[i]);
        scan[tseg * 128 + tp] = c;
        __syncthreads();

        // carry into this segment: C_s = d25*C_{s-1} + L_{s-1}
        float C = 0.0f;
        #pragma unroll
        for (int u = 0; u < 3; ++u)
            if (u < tseg) C = d25 * C + scan[u * 128 + tp];

        // phase 2: emit trace[t] = carry-before-t as bf16 into A [p][t]
        {
            char* arow = smem + (buf ? SM_A1 : SM_A0) + tp * A_ROW_B + tseg * 50;
            #pragma unroll
            for (int i = 0; i < 25; ++i) {
                *(__nv_bfloat16*)(arow + i * 2) = __float2bfloat16(C);
                C = d * (C + xr[i]);
            }
        }
        (void)A; (void)Bb;
    };

    __syncthreads();          // pads done
    prepare(kid, 0);          // batch 0
    __syncthreads();

    // ldmatrix lane addressing
    const int a_row  = (lane & 15);
    const int a_colh = (lane >> 4) * 8;
    const int bg  = lane >> 3;
    const int bl8 = lane & 7;
    const int b_krow = (bg & 1) * 8 + bl8;
    const int b_qoff = (bg >> 1) * 8;

    for (int j = 0; j < nb; ++j) {
        const int buf = j & 1;
        const uint32_t A = smA[buf];
        const uint32_t Bb = smB[buf];

        // ---- MMA over 7 k16 steps ----
        #pragma unroll
        for (int ks = 0; ks < 7; ++ks) {
            uint32_t afrag[4][4];
            uint32_t bfrag[4][2];
            #pragma unroll
            for (int mi = 0; mi < 4; ++mi) {
                uint32_t addr = A + (uint32_t)((warp_m * 64 + mi * 16 + a_row) * A_ROW_B
                                               + (a_colh + ks * 16) * 2);
                ldmatrix_x4(afrag[mi], addr);
            }
            #pragma unroll
            for (int nip = 0; nip < 2; ++nip) {
                uint32_t addr = Bb + (uint32_t)((ks * 16 + b_krow) * B_ROW_B
                                                + (warp_n * 32 + nip * 16 + b_qoff) * 2);
                uint32_t r[4];
                ldmatrix_x4_trans(r, addr);
                bfrag[nip * 2 + 0][0] = r[0]; bfrag[nip * 2 + 0][1] = r[1];
                bfrag[nip * 2 + 1][0] = r[2]; bfrag[nip * 2 + 1][1] = r[3];
            }
            #pragma unroll
            for (int mi = 0; mi < 4; ++mi)
                #pragma unroll
                for (int ni = 0; ni < 4; ++ni)
                    mma_16816(acc[mi][ni], afrag[mi], bfrag[ni]);
        }

        // ---- prepare next batch into other buffer (overlaps MMA drain) ----
        if (j + 1 < nb)
            prepare(kid + (j + 1) * KSPLIT, buf ^ 1);
        __syncthreads();
    }

    // ---- epilogue: fp32 partials ----
    float* part = g_partials + (size_t)kid * (NPRE * NPOST);
    const int p_base = mtile * 128 + warp_m * 64;
    const int q_base = warp_n * 32;
    #pragma unroll
    for (int mi = 0; mi < 4; ++mi) {
        #pragma unroll
        for (int ni = 0; ni < 4; ++ni) {
            int p0 = p_base + mi * 16 + (lane >> 2);
            int q  = q_base + ni * 8 + (lane & 3) * 2;
            *(float2*)(part + (size_t)p0 * NPOST + q)       = make_float2(acc[mi][ni][0], acc[mi][ni][1]);
            *(float2*)(part + (size_t)(p0 + 8) * NPOST + q) = make_float2(acc[mi][ni][2], acc[mi][ni][3]);
        }
    }
}

// ============================================================================
// Reduce partials + scale (float4 per thread)
// ============================================================================
__global__ void stdp_reduce_kernel(float* __restrict__ out) {
    const int idx = blockIdx.x * blockDim.x + threadIdx.x;   // 0..16383
    const float scale = (0.005f - 0.00525f) / (float)KTOT;
    float4 s = make_float4(0.f, 0.f, 0.f, 0.f);
    #pragma unroll 2
    for (int k = 0; k < KSPLIT; ++k) {
        float4 v = *(const float4*)(g_partials + (size_t)k * (NPRE * NPOST) + idx * 4);
        s.x += v.x; s.y += v.y; s.z += v.z; s.w += v.w;
    }
    s.x *= scale; s.y *= scale; s.z *= scale; s.w *= scale;
    *(float4*)(out + idx * 4) = s;
}

// ============================================================================
// Launch
// ============================================================================
extern "C" void kernel_launch(void* const* d_in, const int* in_sizes, int n_in,
                              void* d_out, int out_size) {
    (void)in_sizes; (void)n_in; (void)out_size;
    const float* pre  = (const float*)d_in[0];
    const float* post = (const float*)d_in[1];
    float* out = (float*)d_out;

    cudaFuncSetAttribute(stdp_fused_kernel,
                         cudaFuncAttributeMaxDynamicSharedMemorySize, GEMM_SMEM);

    stdp_fused_kernel<<<dim3(KSPLIT, 2), 512, GEMM_SMEM>>>(pre, post);
    stdp_reduce_kernel<<<64, 256>>>(out);
}

// round 5
// speedup vs baseline: 1.1606x; 1.1215x over previous
#include <cuda_runtime.h>
#include <cuda_bf16.h>
#include <cstdint>

// ============================================================================
// Problem constants
// ============================================================================
#define BB       512
#define TT       100          // K per batch
#define TPAD     112          // padded to 7 x k16
#define NPRE     256
#define NPOST    256
#define KTOT     (BB * TT)    // 51200
#define KSPLIT   74           // grid (74, 2 mtiles) = 148 CTAs = one wave

// A tile (trace bf16, [p][t]): 128 rows, row stride 240B (120 bf16 >= 112)
#define A_ROW_B   240
#define A_TILE_B  (128 * A_ROW_B)       // 30720
// B tile (post bf16, [t][q]): 112 rows, row stride 528B (264 bf16 >= 256)
#define B_ROW_B   528
#define B_TILE_B  (TPAD * B_ROW_B)      // 59136

#define SM_A0     0
#define SM_A1     A_TILE_B                       // 30720
#define SM_B0     (2 * A_TILE_B)                 // 61440
#define SM_B1     (2 * A_TILE_B + B_TILE_B)      // 120576
#define SM_SCAN   (2 * A_TILE_B + 2 * B_TILE_B)  // 179712
#define GEMM_SMEM (SM_SCAN + 4 * 128 * 4)        // 181760

// ============================================================================
// PTX helpers (baseline PTX only — tcgen05 unavailable on plain sm_103 target)
// ============================================================================
__device__ __forceinline__ uint32_t smem_to_u32(const void* smem_ptr) {
    uint32_t addr;
    asm("{ .reg .u64 tmp; cvta.to.shared.u64 tmp, %1; cvt.u32.u64 %0, tmp; }"
        : "=r"(addr) : "l"(smem_ptr));
    return addr;
}

__device__ __forceinline__ void ldmatrix_x4(uint32_t* r, uint32_t addr) {
    asm volatile("ldmatrix.sync.aligned.m8n8.x4.shared.b16 {%0,%1,%2,%3}, [%4];"
                 : "=r"(r[0]), "=r"(r[1]), "=r"(r[2]), "=r"(r[3]) : "r"(addr));
}
__device__ __forceinline__ void ldmatrix_x4_trans(uint32_t* r, uint32_t addr) {
    asm volatile("ldmatrix.sync.aligned.m8n8.x4.trans.shared.b16 {%0,%1,%2,%3}, [%4];"
                 : "=r"(r[0]), "=r"(r[1]), "=r"(r[2]), "=r"(r[3]) : "r"(addr));
}

__device__ __forceinline__ void mma_16816(float* c, const uint32_t* a, const uint32_t* b) {
    asm volatile(
        "mma.sync.aligned.m16n8k16.row.col.f32.bf16.bf16.f32 "
        "{%0,%1,%2,%3}, {%4,%5,%6,%7}, {%8,%9}, {%0,%1,%2,%3};"
        : "+f"(c[0]), "+f"(c[1]), "+f"(c[2]), "+f"(c[3])
        : "r"(a[0]), "r"(a[1]), "r"(a[2]), "r"(a[3]), "r"(b[0]), "r"(b[1]));
}

__device__ __forceinline__ uint32_t pack_bf16x2(float a, float b) {
    return ((uint32_t)__bfloat16_as_ushort(__float2bfloat16(b)) << 16)
         |  (uint32_t)__bfloat16_as_ushort(__float2bfloat16(a));
}

// ============================================================================
// Kernel 0: zero the output (d_out is poisoned; atomics need a clean base)
// ============================================================================
__global__ void stdp_zero_kernel(float4* __restrict__ out) {
    out[blockIdx.x * blockDim.x + threadIdx.x] = make_float4(0.f, 0.f, 0.f, 0.f);
}

// ============================================================================
// Fused kernel: trace recurrence + post convert + split-K bf16 HMMA GEMM
//   grid (74, 2), 512 threads = 16 warps (2 M x 8 N), warp tile 64x32
//   Epilogue: scaled atomicAdd (RED) directly into d_out.
// ============================================================================
__global__ void __launch_bounds__(512, 1) stdp_fused_kernel(
    const float* __restrict__ pre, const float* __restrict__ post,
    float* __restrict__ out)
{
    extern __shared__ __align__(16) char smem[];
    const uint32_t su = smem_to_u32(smem);
    float* scan = (float*)(smem + SM_SCAN);      // [4][128]

    const int tid    = threadIdx.x;
    const int wid    = tid >> 5;
    const int lane   = tid & 31;
    const int kid    = blockIdx.x;
    const int mtile  = blockIdx.y;
    const int warp_m = wid >> 3;       // 0..1
    const int warp_n = wid & 7;        // 0..7

    // trace-compute role: p in [0,128), seg in [0,4) covering 25 t each
    const int tp   = tid & 127;
    const int tseg = tid >> 7;

    const float d   = 0.95122942450071403f;   // exp(-1/20)
    const float d25 = 0.28650479686019010f;   // exp(-25/20)

    const uint32_t smA[2] = { su + SM_A0, su + SM_A1 };
    const uint32_t smB[2] = { su + SM_B0, su + SM_B1 };

    // ---- zero pads (t in [100,TPAD)) once; batches only write t < 100 ----
    for (int i = tid; i < 2 * 128 * 10; i += 512) {      // A: bytes [200,240) per row
        int bufrow = i / 10;
        int off    = (i % 10) * 4;
        *(uint32_t*)(smem + SM_A0 + bufrow * A_ROW_B + 200 + off) = 0u;
    }
    for (int i = tid; i < 2 * 12 * (B_ROW_B / 4); i += 512) {   // B rows [100,112)
        int half = i / (12 * (B_ROW_B / 4));
        int rem  = i % (12 * (B_ROW_B / 4));
        int row  = 100 + rem / (B_ROW_B / 4);
        int off  = (rem % (B_ROW_B / 4)) * 4;
        *(uint32_t*)(smem + (half ? SM_B1 : SM_B0) + row * B_ROW_B + off) = 0u;
    }

    float acc[4][4][4];
    #pragma unroll
    for (int i = 0; i < 4; ++i)
        #pragma unroll
        for (int j = 0; j < 4; ++j)
            #pragma unroll
            for (int c = 0; c < 4; ++c) acc[i][j][c] = 0.0f;

    const int nb = (BB - kid + KSPLIT - 1) / KSPLIT;   // 6 or 7 batches

    // ---- prepare(batch, buf): build A (trace) and B (post) bf16 tiles ----
    auto prepare = [&](int b, int buf) {
        // pre loads: thread (tp, tseg) reads 25 consecutive-t values of its p
        float xr[25];
        {
            const float* src = pre + ((size_t)b * TT + tseg * 25) * NPRE + mtile * 128 + tp;
            #pragma unroll
            for (int i = 0; i < 25; ++i)
                xr[i] = src[(size_t)i * NPRE];
        }

        // post: 6400 float4 chunks; convert to bf16, STS into B tile [t][q]
        {
            const float4* psrc = (const float4*)(post + (size_t)b * TT * NPOST);
            #pragma unroll
            for (int it = 0; it < 13; ++it) {
                int f = tid + it * 512;
                if (f < 6400) {
                    int t = f >> 6, qg = f & 63;
                    float4 v = psrc[t * 64 + qg];
                    uint2 pk = make_uint2(pack_bf16x2(v.x, v.y), pack_bf16x2(v.z, v.w));
                    *(uint2*)(smem + (buf ? SM_B1 : SM_B0) + t * B_ROW_B + qg * 8) = pk;
                }
            }
        }

        // phase 1: local decayed sum over this segment
        float c = 0.0f;
        #pragma unroll
        for (int i = 0; i < 25; ++i)
            c = d * (c + xr[i]);
        scan[tseg * 128 + tp] = c;
        __syncthreads();

        // carry into this segment: C_s = d25*C_{s-1} + L_{s-1}
        float C = 0.0f;
        #pragma unroll
        for (int u = 0; u < 3; ++u)
            if (u < tseg) C = d25 * C + scan[u * 128 + tp];

        // phase 2: emit trace[t] = carry-before-t as bf16 into A [p][t]
        {
            char* arow = smem + (buf ? SM_A1 : SM_A0) + tp * A_ROW_B + tseg * 50;
            #pragma unroll
            for (int i = 0; i < 25; ++i) {
                *(__nv_bfloat16*)(arow + i * 2) = __float2bfloat16(C);
                C = d * (C + xr[i]);
            }
        }
    };

    __syncthreads();          // pads done
    prepare(kid, 0);          // batch 0
    __syncthreads();

    // ldmatrix lane addressing
    const int a_row  = (lane & 15);
    const int a_colh = (lane >> 4) * 8;
    const int bg  = lane >> 3;
    const int bl8 = lane & 7;
    const int b_krow = (bg & 1) * 8 + bl8;
    const int b_qoff = (bg >> 1) * 8;

    for (int j = 0; j < nb; ++j) {
        const int buf = j & 1;
        const uint32_t A = smA[buf];
        const uint32_t Bb = smB[buf];

        // ---- MMA over 7 k16 steps ----
        #pragma unroll
        for (int ks = 0; ks < 7; ++ks) {
            uint32_t afrag[4][4];
            uint32_t bfrag[4][2];
            #pragma unroll
            for (int mi = 0; mi < 4; ++mi) {
                uint32_t addr = A + (uint32_t)((warp_m * 64 + mi * 16 + a_row) * A_ROW_B
                                               + (a_colh + ks * 16) * 2);
                ldmatrix_x4(afrag[mi], addr);
            }
            #pragma unroll
            for (int nip = 0; nip < 2; ++nip) {
                uint32_t addr = Bb + (uint32_t)((ks * 16 + b_krow) * B_ROW_B
                                                + (warp_n * 32 + nip * 16 + b_qoff) * 2);
                uint32_t r[4];
                ldmatrix_x4_trans(r, addr);
                bfrag[nip * 2 + 0][0] = r[0]; bfrag[nip * 2 + 0][1] = r[1];
                bfrag[nip * 2 + 1][0] = r[2]; bfrag[nip * 2 + 1][1] = r[3];
            }
            #pragma unroll
            for (int mi = 0; mi < 4; ++mi)
                #pragma unroll
                for (int ni = 0; ni < 4; ++ni)
                    mma_16816(acc[mi][ni], afrag[mi], bfrag[ni]);
        }

        // ---- prepare next batch into other buffer ----
        if (j + 1 < nb)
            prepare(kid + (j + 1) * KSPLIT, buf ^ 1);
        __syncthreads();
    }

    // ---- epilogue: scale + RED atomics straight into d_out ----
    const float scale = (0.005f - 0.00525f) / (float)KTOT;
    const int p_base = mtile * 128 + warp_m * 64;
    const int q_base = warp_n * 32;
    #pragma unroll
    for (int mi = 0; mi < 4; ++mi) {
        #pragma unroll
        for (int ni = 0; ni < 4; ++ni) {
            int p0 = p_base + mi * 16 + (lane >> 2);
            int q  = q_base + ni * 8 + (lane & 3) * 2;
            float* o0 = out + (size_t)p0 * NPOST + q;
            float* o1 = out + (size_t)(p0 + 8) * NPOST + q;
            atomicAdd(o0,     acc[mi][ni][0] * scale);
            atomicAdd(o0 + 1, acc[mi][ni][1] * scale);
            atomicAdd(o1,     acc[mi][ni][2] * scale);
            atomicAdd(o1 + 1, acc[mi][ni][3] * scale);
        }
    }
}

// ============================================================================
// Launch
// ============================================================================
extern "C" void kernel_launch(void* const* d_in, const int* in_sizes, int n_in,
                              void* d_out, int out_size) {
    (void)in_sizes; (void)n_in; (void)out_size;
    const float* pre  = (const float*)d_in[0];
    const float* post = (const float*)d_in[1];
    float* out = (float*)d_out;

    cudaFuncSetAttribute(stdp_fused_kernel,
                         cudaFuncAttributeMaxDynamicSharedMemorySize, GEMM_SMEM);

    stdp_zero_kernel<<<64, 256>>>((float4*)out);   // 65536 floats
    stdp_fused_kernel<<<dim3(KSPLIT, 2), 512, GEMM_SMEM>>>(pre, post, out);
}